// round 8
// baseline (speedup 1.0000x reference)
#include <cuda_runtime.h>

#define NN   50000
#define EE   300000
#define ETOT 900000
#define CC   2
#define TT   3
#define HD   64
#define CH   ((size_t)NN * HD)          // per-channel plane size
// scan config
#define SCAN_T 512
#define SCAN_I 8
#define SCAN_CHUNK (SCAN_T * SCAN_I)    // 4096

#define PROJ_BLKS ((NN + 63) / 64)          // 782
#define HIST_BLKS ((ETOT + 1023) / 1024)    // 879

// ---------------- device scratch (static, allowed) ----------------
__device__ int   g_cnt[NN];
__device__ int   g_rowptr[NN + 1];
__device__ int   g_cursor[NN];
__device__ int   g_bsum[64];
__device__ int2  g_edge[ETOT];            // {col | (etype<<28), float bits}
__device__ float g_H0[(size_t)CC * NN * HD];
__device__ float g_H1[(size_t)CC * NN * HD];
__device__ float g_X0[(size_t)CC * NN * HD];

// ---------------- fused: histogram (block 1 CSR) + projection (block 1) -------
// blocks [0, PROJ_BLKS): H[c] = X @ Ws0[c], X0 = H  (warp/row, lane = 2 cols/ch)
// blocks [PROJ_BLKS, PROJ_BLKS+HIST_BLKS): row-degree histogram, 4 edges/thread
__global__ __launch_bounds__(256) void k_hist_proj(
        const float* __restrict__ X, const float* __restrict__ Ws,
        const int* __restrict__ ei0, const int* __restrict__ ei1,
        const int* __restrict__ ei2) {
    if (blockIdx.x < PROJ_BLKS) {
        __shared__ float wsm[2 * HD * HD];  // 32 KB
        for (int i = threadIdx.x; i < 2 * HD * HD; i += 256) wsm[i] = __ldg(&Ws[i]);
        __syncthreads();
        int warp = threadIdx.x >> 5, lane = threadIdx.x & 31;
        int rowBase = blockIdx.x * 64;
        const float2* __restrict__ w0 = (const float2*)wsm;
        const float2* __restrict__ w1 = (const float2*)(wsm + HD * HD);
        for (int rr = warp; rr < 64; rr += 8) {
            int row = rowBase + rr;
            if (row >= NN) break;
            float x0 = X[(size_t)row * HD + lane];
            float x1 = X[(size_t)row * HD + 32 + lane];
            float2 a0 = {0.f, 0.f}, a1 = {0.f, 0.f};
#pragma unroll
            for (int k = 0; k < HD; k++) {
                float xk = __shfl_sync(0xffffffffu, (k < 32) ? x0 : x1, k & 31);
                float2 v0 = w0[k * 32 + lane];
                float2 v1 = w1[k * 32 + lane];
                a0.x = fmaf(xk, v0.x, a0.x); a0.y = fmaf(xk, v0.y, a0.y);
                a1.x = fmaf(xk, v1.x, a1.x); a1.y = fmaf(xk, v1.y, a1.y);
            }
            size_t o0 = ((size_t)row) * HD + 2 * lane;
            size_t o1 = o0 + CH;
            *(float2*)(g_H0 + o0) = a0;  *(float2*)(g_X0 + o0) = a0;
            *(float2*)(g_H0 + o1) = a1;  *(float2*)(g_X0 + o1) = a1;
        }
    } else {
        int base = (blockIdx.x - PROJ_BLKS) * 1024 + threadIdx.x;
#pragma unroll
        for (int k = 0; k < 4; k++) {
            int e = base + k * 256;
            if (e >= ETOT) break;
            const int* ei; int le;
            if (e < EE)           { ei = ei0; le = e; }
            else if (e < 2 * EE)  { ei = ei1; le = e - EE; }
            else                  { ei = ei2; le = e - 2 * EE; }
            atomicAdd(&g_cnt[ei[le]], 1);
        }
    }
}

// ---------------- CSR scan ----------------
__global__ void k_scan1() {
    __shared__ int s[SCAN_T];
    int t = threadIdx.x;
    int base = blockIdx.x * SCAN_CHUNK + t * SCAN_I;
    int v[SCAN_I];
    int sum = 0;
#pragma unroll
    for (int i = 0; i < SCAN_I; i++) {
        int idx = base + i;
        v[i] = (idx < NN) ? g_cnt[idx] : 0;
        sum += v[i];
    }
    s[t] = sum;
    __syncthreads();
    for (int off = 1; off < SCAN_T; off <<= 1) {
        int x = (t >= off) ? s[t - off] : 0;
        __syncthreads();
        if (t >= off) s[t] += x;
        __syncthreads();
    }
    int excl = s[t] - sum;
    if (t == SCAN_T - 1) g_bsum[blockIdx.x] = s[t];
    int run = excl;
#pragma unroll
    for (int i = 0; i < SCAN_I; i++) {
        int idx = base + i;
        if (idx < NN) g_rowptr[idx] = run;
        run += v[i];
    }
}

__global__ void k_scan3() {
    int i = blockIdx.x * blockDim.x + threadIdx.x;
    if (i >= NN) return;
    int blk = i / SCAN_CHUNK;
    int off = 0;
    for (int b = 0; b < blk; b++) off += g_bsum[b];
    int val = g_rowptr[i] + off;
    g_rowptr[i] = val;
    g_cursor[i] = val;
    if (i == 0) g_rowptr[NN] = ETOT;
}

__global__ void k_scatter(const int* __restrict__ ei0, const int* __restrict__ ei1,
                          const int* __restrict__ ei2,
                          const float* __restrict__ ev0, const float* __restrict__ ev1,
                          const float* __restrict__ ev2) {
    int e = blockIdx.x * blockDim.x + threadIdx.x;
    if (e >= ETOT) return;
    const int* ei; const float* ev; int le; int t;
    if (e < EE)          { ei = ei0; ev = ev0; le = e;           t = 0; }
    else if (e < 2 * EE) { ei = ei1; ev = ev1; le = e - EE;      t = 1; }
    else                 { ei = ei2; ev = ev2; le = e - 2 * EE;  t = 2; }
    int r   = ei[le];
    int cix = ei[EE + le];
    float v = ev[le];
    int p = atomicAdd(&g_cursor[r], 1);
    g_edge[p] = make_int2(cix | (t << 28), __float_as_int(v));
}

// ---------------- SpMM (both channels, half-warp float4 gathers) ----------------
// warp per row. dir=0: g_H0 -> g_H1, dir=1: g_H1 -> g_H0 (both channel planes).
__global__ __launch_bounds__(256) void k_spmm(int dir, const float* __restrict__ layW) {
    const float* __restrict__ Hin  = dir ? g_H1 : g_H0;
    float* __restrict__       Hout = dir ? g_H0 : g_H1;
    int warp = threadIdx.x >> 5, lane = threadIdx.x & 31;
    int sub = lane >> 4, laneq = lane & 15;
    int r = blockIdx.x * 8 + warp;
    if (r >= NN) return;

    // softmax over T=3 for each channel
    float f0[TT], f1[TT];
    {
        float b0 = __ldg(&layW[0]), b1 = __ldg(&layW[1]), b2 = __ldg(&layW[2]);
        float mx = fmaxf(b0, fmaxf(b1, b2));
        float e0 = __expf(b0 - mx), e1 = __expf(b1 - mx), e2 = __expf(b2 - mx);
        float inv = 1.0f / (e0 + e1 + e2);
        f0[0] = e0 * inv; f0[1] = e1 * inv; f0[2] = e2 * inv;
        b0 = __ldg(&layW[3]); b1 = __ldg(&layW[4]); b2 = __ldg(&layW[5]);
        mx = fmaxf(b0, fmaxf(b1, b2));
        e0 = __expf(b0 - mx); e1 = __expf(b1 - mx); e2 = __expf(b2 - mx);
        inv = 1.0f / (e0 + e1 + e2);
        f1[0] = e0 * inv; f1[1] = e1 * inv; f1[2] = e2 * inv;
    }

    int start = g_rowptr[r];
    int end   = g_rowptr[r + 1];
    float4 acc0 = {0.f, 0.f, 0.f, 0.f};
    float4 acc1 = {0.f, 0.f, 0.f, 0.f};

    for (int base = start; base < end; base += 32) {
        int e = base + lane;
        float wa = 0.f, wb = 0.f;
        int ci = 0;
        if (e < end) {
            int2 md = __ldg(&g_edge[e]);
            float v = __int_as_float(md.y);
            int et  = md.x >> 28;
            ci = md.x & 0x0FFFFFFF;
            float fa = (et == 0) ? f0[0] : ((et == 1) ? f0[1] : f0[2]);
            float fb = (et == 0) ? f1[0] : ((et == 1) ? f1[1] : f1[2]);
            wa = v * fa;
            wb = v * fb;
        }
        int mm = end - base;
        if (mm > 32) mm = 32;
        int mm2 = (mm + 1) & ~1;    // lanes >= mm carry w=0, so padding is safe

#define SPMM_PAIR(J)                                                          \
        {                                                                     \
            int src = (J) + sub;                                              \
            int   cj = __shfl_sync(0xffffffffu, ci, src);                     \
            float ua = __shfl_sync(0xffffffffu, wa, src);                     \
            float ub = __shfl_sync(0xffffffffu, wb, src);                     \
            float4 h0 = *((const float4*)(Hin + (((size_t)cj) << 6)) + laneq);\
            float4 h1 = *((const float4*)(Hin + CH + (((size_t)cj) << 6)) + laneq);\
            acc0.x = fmaf(ua, h0.x, acc0.x); acc0.y = fmaf(ua, h0.y, acc0.y); \
            acc0.z = fmaf(ua, h0.z, acc0.z); acc0.w = fmaf(ua, h0.w, acc0.w); \
            acc1.x = fmaf(ub, h1.x, acc1.x); acc1.y = fmaf(ub, h1.y, acc1.y); \
            acc1.z = fmaf(ub, h1.z, acc1.z); acc1.w = fmaf(ub, h1.w, acc1.w); \
        }

        int j = 0;
        for (; j + 8 <= mm2; j += 8) {
#pragma unroll
            for (int p = 0; p < 4; p++) SPMM_PAIR(j + 2 * p);
        }
        for (; j < mm2; j += 2) SPMM_PAIR(j);
#undef SPMM_PAIR
    }

    // combine the two half-warps (each accumulated every other edge)
    acc0.x += __shfl_xor_sync(0xffffffffu, acc0.x, 16);
    acc0.y += __shfl_xor_sync(0xffffffffu, acc0.y, 16);
    acc0.z += __shfl_xor_sync(0xffffffffu, acc0.z, 16);
    acc0.w += __shfl_xor_sync(0xffffffffu, acc0.w, 16);
    acc1.x += __shfl_xor_sync(0xffffffffu, acc1.x, 16);
    acc1.y += __shfl_xor_sync(0xffffffffu, acc1.y, 16);
    acc1.z += __shfl_xor_sync(0xffffffffu, acc1.z, 16);
    acc1.w += __shfl_xor_sync(0xffffffffu, acc1.w, 16);

    float4 outv = (sub == 0) ? acc0 : acc1;
    size_t off = ((size_t)sub) * CH + ((size_t)r << 6) + 4 * laneq;
    *(float4*)(Hout + off) = outv;
}

// ---------------- fused: combine + linear1 + relu + projection (block 2) ------
// Reads g_X0 and final block-1 H (in g_H0), computes Hm and Y=relu(Hm@linW+b)
// entirely in registers, then immediately projects Y through Ws1 (both
// channels), writing the block-2 initial H into g_H0/g_X0. No g_mid traffic.
// dynamic smem: [0, 8192) floats = linW (128x64), [8192, 16384) = Ws1 (2x64x64)
__global__ __launch_bounds__(256) void k_lin_proj(const float* __restrict__ linW,
                                                  const float* __restrict__ linb,
                                                  const float* __restrict__ Ws) {
    extern __shared__ float sm[];
    float* lsm = sm;             // 8192 floats
    float* psm = sm + 8192;      // 8192 floats
    for (int i = threadIdx.x; i < 2 * HD * HD; i += 256) {
        lsm[i] = __ldg(&linW[i]);
        psm[i] = __ldg(&Ws[i]);
    }
    __syncthreads();
    int warp = threadIdx.x >> 5, lane = threadIdx.x & 31;
    int rowBase = blockIdx.x * 64;
    const float2* __restrict__ lw = (const float2*)lsm;
    const float2* __restrict__ w0 = (const float2*)psm;
    const float2* __restrict__ w1 = (const float2*)(psm + HD * HD);
    float2 bias = {__ldg(&linb[2 * lane]), __ldg(&linb[2 * lane + 1])};
    for (int rr = warp; rr < 64; rr += 8) {
        int row = rowBase + rr;
        if (row >= NN) break;
        float xv[4];
#pragma unroll
        for (int t = 0; t < 4; t++) {
            int k = lane + 32 * t;      // k in [0,128): c = k>>6, j = k&63
            int cch = k >> 6, j = k & 63;
            size_t o = ((size_t)cch) * CH + ((size_t)row) * HD + j;
            float a = g_X0[o];
            float h = g_H0[o];
            float m = 0.5f * a + 0.5f * h;
            m = m > 0.f ? m : 0.f;
            xv[t] = 0.8f * m + 0.2f * a;
        }
        float2 acc = bias;
#pragma unroll
        for (int k = 0; k < 2 * HD; k++) {
            float xk = __shfl_sync(0xffffffffu, xv[k >> 5], k & 31);
            float2 wv = lw[k * 32 + lane];
            acc.x = fmaf(xk, wv.x, acc.x);
            acc.y = fmaf(xk, wv.y, acc.y);
        }
        acc.x = acc.x > 0.f ? acc.x : 0.f;   // Y row: lane owns cols 2*lane, 2*lane+1
        acc.y = acc.y > 0.f ? acc.y : 0.f;
        // project Y row through Ws1 (both channels) without leaving registers
        float2 a0 = {0.f, 0.f}, a1 = {0.f, 0.f};
#pragma unroll
        for (int k = 0; k < HD; k++) {
            float xk = __shfl_sync(0xffffffffu, (k & 1) ? acc.y : acc.x, k >> 1);
            float2 v0 = w0[k * 32 + lane];
            float2 v1 = w1[k * 32 + lane];
            a0.x = fmaf(xk, v0.x, a0.x); a0.y = fmaf(xk, v0.y, a0.y);
            a1.x = fmaf(xk, v1.x, a1.x); a1.y = fmaf(xk, v1.y, a1.y);
        }
        size_t o0 = ((size_t)row) * HD + 2 * lane;
        size_t o1 = o0 + CH;
        *(float2*)(g_H0 + o0) = a0;  *(float2*)(g_X0 + o0) = a0;
        *(float2*)(g_H0 + o1) = a1;  *(float2*)(g_X0 + o1) = a1;
    }
}

// ---------------- final combine + linear + relu -> d_out ----------------
__global__ __launch_bounds__(256) void k_lin(const float* __restrict__ linW,
                                             const float* __restrict__ linb,
                                             float* __restrict__ Y) {
    __shared__ float wsm[2 * HD * HD];  // 32 KB
    for (int i = threadIdx.x; i < 2 * HD * HD; i += 256) wsm[i] = __ldg(&linW[i]);
    __syncthreads();
    int warp = threadIdx.x >> 5, lane = threadIdx.x & 31;
    int rowBase = blockIdx.x * 64;
    const float2* __restrict__ wsm2 = (const float2*)wsm;
    float2 bias = {__ldg(&linb[2 * lane]), __ldg(&linb[2 * lane + 1])};
    for (int rr = warp; rr < 64; rr += 8) {
        int row = rowBase + rr;
        if (row >= NN) break;
        float xv[4];
#pragma unroll
        for (int t = 0; t < 4; t++) {
            int k = lane + 32 * t;
            int cch = k >> 6, j = k & 63;
            size_t o = ((size_t)cch) * CH + ((size_t)row) * HD + j;
            float a = g_X0[o];
            float h = g_H0[o];
            float m = 0.5f * a + 0.5f * h;
            m = m > 0.f ? m : 0.f;
            xv[t] = 0.8f * m + 0.2f * a;
        }
        float2 acc = bias;
#pragma unroll
        for (int k = 0; k < 2 * HD; k++) {
            float xk = __shfl_sync(0xffffffffu, xv[k >> 5], k & 31);
            float2 wv = wsm2[k * 32 + lane];
            acc.x = fmaf(xk, wv.x, acc.x);
            acc.y = fmaf(xk, wv.y, acc.y);
        }
        acc.x = acc.x > 0.f ? acc.x : 0.f;
        acc.y = acc.y > 0.f ? acc.y : 0.f;
        *(float2*)(Y + (size_t)row * HD + 2 * lane) = acc;
    }
}

// ---------------- launch ----------------
extern "C" void kernel_launch(void* const* d_in, const int* in_sizes, int n_in,
                              void* d_out, int out_size) {
    const float* X     = (const float*)d_in[0];
    const float* ev0   = (const float*)d_in[1];
    const float* ev1   = (const float*)d_in[2];
    const float* ev2   = (const float*)d_in[3];
    const float* Ws0   = (const float*)d_in[4];
    const float* Ws1   = (const float*)d_in[5];
    const float* lW0   = (const float*)d_in[6];
    const float* lW1   = (const float*)d_in[7];
    const float* linW0 = (const float*)d_in[8];
    const float* linb0 = (const float*)d_in[9];
    const float* linW1 = (const float*)d_in[10];
    const float* linb1 = (const float*)d_in[11];
    const int*   ei0   = (const int*)d_in[12];
    const int*   ei1   = (const int*)d_in[13];
    const int*   ei2   = (const int*)d_in[14];

    cudaFuncSetAttribute(k_lin_proj, cudaFuncAttributeMaxDynamicSharedMemorySize,
                         16384 * sizeof(float));

    // ---- CSR build overlapped with block-1 projection ----
    void* cntPtr = nullptr;
    cudaGetSymbolAddress(&cntPtr, g_cnt);
    cudaMemsetAsync(cntPtr, 0, NN * sizeof(int), 0);                   // 1
    k_hist_proj<<<PROJ_BLKS + HIST_BLKS, 256>>>(X, Ws0, ei0, ei1, ei2); // 2
    k_scan1<<<(NN + SCAN_CHUNK - 1) / SCAN_CHUNK, SCAN_T>>>();          // 3
    k_scan3<<<(NN + 255) / 256, 256>>>();                               // 4
    k_scatter<<<(ETOT + 255) / 256, 256>>>(ei0, ei1, ei2, ev0, ev1, ev2); // 5

    dim3 gs((NN + 7) / 8);

    // ---- block 1 GT layers ----
    k_spmm<<<gs, 256>>>(0, lW0);             // 6  <- ncu -s 5 -c 1 window
    k_spmm<<<gs, 256>>>(1, lW0 + CC * TT);   // 7

    // ---- block1 epilogue fused with block2 projection ----
    k_lin_proj<<<PROJ_BLKS, 256, 16384 * sizeof(float)>>>(linW0, linb0, Ws1); // 8

    // ---- block 2 GT layers + output ----
    k_spmm<<<gs, 256>>>(0, lW1);             // 9
    k_spmm<<<gs, 256>>>(1, lW1 + CC * TT);   // 10
    k_lin<<<PROJ_BLKS, 256>>>(linW1, linb1, (float*)d_out);             // 11
}

// round 10
// speedup vs baseline: 1.0832x; 1.0832x over previous
#include <cuda_runtime.h>

#define NN   50000
#define EE   300000
#define ETOT 900000
#define CC   2
#define TT   3
#define HD   64
#define CH   ((size_t)NN * HD)          // per-channel plane size
// scan config
#define SCAN_T 512
#define SCAN_I 8
#define SCAN_CHUNK (SCAN_T * SCAN_I)    // 4096

#define PROJ_BLKS ((NN + 63) / 64)          // 782
#define HIST_BLKS ((ETOT + 1023) / 1024)    // 879

// ---------------- device scratch (static, allowed; zero-initialized at load) --
__device__ int   g_cnt[NN];               // invariant: zero at kernel_launch entry
__device__ int   g_rowptr[NN + 1];
__device__ int   g_cursor[NN];
__device__ int   g_bsum[64];
__device__ int2  g_edge[ETOT];            // {col | (etype<<28), float bits}
__device__ float g_H0[(size_t)CC * NN * HD];
__device__ float g_H1[(size_t)CC * NN * HD];
__device__ float g_X0[(size_t)CC * NN * HD];

// ---------------- fused: histogram (CSR degree) + projection (block 1) --------
__global__ __launch_bounds__(256) void k_hist_proj(
        const float* __restrict__ X, const float* __restrict__ Ws,
        const int* __restrict__ ei0, const int* __restrict__ ei1,
        const int* __restrict__ ei2) {
    if (blockIdx.x < PROJ_BLKS) {
        __shared__ float wsm[2 * HD * HD];  // 32 KB
        for (int i = threadIdx.x; i < 2 * HD * HD; i += 256) wsm[i] = __ldg(&Ws[i]);
        __syncthreads();
        int warp = threadIdx.x >> 5, lane = threadIdx.x & 31;
        int rowBase = blockIdx.x * 64;
        const float2* __restrict__ w0 = (const float2*)wsm;
        const float2* __restrict__ w1 = (const float2*)(wsm + HD * HD);
        for (int rr = warp; rr < 64; rr += 8) {
            int row = rowBase + rr;
            if (row >= NN) break;
            float x0 = X[(size_t)row * HD + lane];
            float x1 = X[(size_t)row * HD + 32 + lane];
            float2 a0 = {0.f, 0.f}, a1 = {0.f, 0.f};
#pragma unroll
            for (int k = 0; k < HD; k++) {
                float xk = __shfl_sync(0xffffffffu, (k < 32) ? x0 : x1, k & 31);
                float2 v0 = w0[k * 32 + lane];
                float2 v1 = w1[k * 32 + lane];
                a0.x = fmaf(xk, v0.x, a0.x); a0.y = fmaf(xk, v0.y, a0.y);
                a1.x = fmaf(xk, v1.x, a1.x); a1.y = fmaf(xk, v1.y, a1.y);
            }
            size_t o0 = ((size_t)row) * HD + 2 * lane;
            size_t o1 = o0 + CH;
            *(float2*)(g_H0 + o0) = a0;  *(float2*)(g_X0 + o0) = a0;
            *(float2*)(g_H0 + o1) = a1;  *(float2*)(g_X0 + o1) = a1;
        }
    } else {
        int base = (blockIdx.x - PROJ_BLKS) * 1024 + threadIdx.x;
#pragma unroll
        for (int k = 0; k < 4; k++) {
            int e = base + k * 256;
            if (e >= ETOT) break;
            const int* ei; int le;
            if (e < EE)           { ei = ei0; le = e; }
            else if (e < 2 * EE)  { ei = ei1; le = e - EE; }
            else                  { ei = ei2; le = e - 2 * EE; }
            atomicAdd(&g_cnt[ei[le]], 1);
        }
    }
}

// ---------------- CSR scan (consumes AND re-zeroes g_cnt) ----------------
__global__ void k_scan1() {
    __shared__ int s[SCAN_T];
    int t = threadIdx.x;
    int base = blockIdx.x * SCAN_CHUNK + t * SCAN_I;
    int v[SCAN_I];
    int sum = 0;
#pragma unroll
    for (int i = 0; i < SCAN_I; i++) {
        int idx = base + i;
        v[i] = (idx < NN) ? g_cnt[idx] : 0;
        if (idx < NN) g_cnt[idx] = 0;      // restore invariant for next launch
        sum += v[i];
    }
    s[t] = sum;
    __syncthreads();
    for (int off = 1; off < SCAN_T; off <<= 1) {
        int x = (t >= off) ? s[t - off] : 0;
        __syncthreads();
        if (t >= off) s[t] += x;
        __syncthreads();
    }
    int excl = s[t] - sum;
    if (t == SCAN_T - 1) g_bsum[blockIdx.x] = s[t];
    int run = excl;
#pragma unroll
    for (int i = 0; i < SCAN_I; i++) {
        int idx = base + i;
        if (idx < NN) g_rowptr[idx] = run;
        run += v[i];
    }
}

__global__ void k_scan3() {
    int i = blockIdx.x * blockDim.x + threadIdx.x;
    if (i >= NN) return;
    int blk = i / SCAN_CHUNK;
    int off = 0;
    for (int b = 0; b < blk; b++) off += g_bsum[b];
    int val = g_rowptr[i] + off;
    g_rowptr[i] = val;
    g_cursor[i] = val;
    if (i == 0) g_rowptr[NN] = ETOT;
}

__global__ void k_scatter(const int* __restrict__ ei0, const int* __restrict__ ei1,
                          const int* __restrict__ ei2,
                          const float* __restrict__ ev0, const float* __restrict__ ev1,
                          const float* __restrict__ ev2) {
    int e = blockIdx.x * blockDim.x + threadIdx.x;
    if (e >= ETOT) return;
    const int* ei; const float* ev; int le; int t;
    if (e < EE)          { ei = ei0; ev = ev0; le = e;           t = 0; }
    else if (e < 2 * EE) { ei = ei1; ev = ev1; le = e - EE;      t = 1; }
    else                 { ei = ei2; ev = ev2; le = e - 2 * EE;  t = 2; }
    int r   = ei[le];
    int cix = ei[EE + le];
    float v = ev[le];
    int p = atomicAdd(&g_cursor[r], 1);
    g_edge[p] = make_int2(cix | (t << 28), __float_as_int(v));
}

// ---------------- SpMM (both channels, half-warp float4 gathers, MLP=16) ------
// warp per row. dir=0: g_H0 -> g_H1, dir=1: g_H1 -> g_H0 (both channel planes).
__global__ __launch_bounds__(256) void k_spmm(int dir, const float* __restrict__ layW) {
    const float* __restrict__ Hin  = dir ? g_H1 : g_H0;
    float* __restrict__       Hout = dir ? g_H0 : g_H1;
    int warp = threadIdx.x >> 5, lane = threadIdx.x & 31;
    int sub = lane >> 4, laneq = lane & 15;
    int r = blockIdx.x * 8 + warp;
    if (r >= NN) return;

    // softmax over T=3 for each channel
    float f0[TT], f1[TT];
    {
        float b0 = __ldg(&layW[0]), b1 = __ldg(&layW[1]), b2 = __ldg(&layW[2]);
        float mx = fmaxf(b0, fmaxf(b1, b2));
        float e0 = __expf(b0 - mx), e1 = __expf(b1 - mx), e2 = __expf(b2 - mx);
        float inv = 1.0f / (e0 + e1 + e2);
        f0[0] = e0 * inv; f0[1] = e1 * inv; f0[2] = e2 * inv;
        b0 = __ldg(&layW[3]); b1 = __ldg(&layW[4]); b2 = __ldg(&layW[5]);
        mx = fmaxf(b0, fmaxf(b1, b2));
        e0 = __expf(b0 - mx); e1 = __expf(b1 - mx); e2 = __expf(b2 - mx);
        inv = 1.0f / (e0 + e1 + e2);
        f1[0] = e0 * inv; f1[1] = e1 * inv; f1[2] = e2 * inv;
    }

    int start = g_rowptr[r];
    int end   = g_rowptr[r + 1];
    float4 acc0 = {0.f, 0.f, 0.f, 0.f};
    float4 acc1 = {0.f, 0.f, 0.f, 0.f};

    for (int base = start; base < end; base += 32) {
        int e = base + lane;
        float wa = 0.f, wb = 0.f;
        int ci = 0;
        if (e < end) {
            int2 md = __ldg(&g_edge[e]);
            float v = __int_as_float(md.y);
            int et  = md.x >> 28;
            ci = md.x & 0x0FFFFFFF;
            float fa = (et == 0) ? f0[0] : ((et == 1) ? f0[1] : f0[2]);
            float fb = (et == 0) ? f1[0] : ((et == 1) ? f1[1] : f1[2]);
            wa = v * fa;
            wb = v * fb;
        }
        int mm = end - base;
        if (mm > 32) mm = 32;
        int mm2 = (mm + 1) & ~1;    // lanes >= mm carry w=0, so padding is safe

#define SPMM_PAIR(J)                                                          \
        {                                                                     \
            int src = (J) + sub;                                              \
            int   cj = __shfl_sync(0xffffffffu, ci, src);                     \
            float ua = __shfl_sync(0xffffffffu, wa, src);                     \
            float ub = __shfl_sync(0xffffffffu, wb, src);                     \
            float4 h0 = *((const float4*)(Hin + (((size_t)cj) << 6)) + laneq);\
            float4 h1 = *((const float4*)(Hin + CH + (((size_t)cj) << 6)) + laneq);\
            acc0.x = fmaf(ua, h0.x, acc0.x); acc0.y = fmaf(ua, h0.y, acc0.y); \
            acc0.z = fmaf(ua, h0.z, acc0.z); acc0.w = fmaf(ua, h0.w, acc0.w); \
            acc1.x = fmaf(ub, h1.x, acc1.x); acc1.y = fmaf(ub, h1.y, acc1.y); \
            acc1.z = fmaf(ub, h1.z, acc1.z); acc1.w = fmaf(ub, h1.w, acc1.w); \
        }

        int j = 0;
        // 8-pair tier: 16 independent LDG.128 in flight
        for (; j + 16 <= mm2; j += 16) {
#pragma unroll
            for (int p = 0; p < 8; p++) SPMM_PAIR(j + 2 * p);
        }
        // 4-pair tier
        if (j + 8 <= mm2) {
#pragma unroll
            for (int p = 0; p < 4; p++) SPMM_PAIR(j + 2 * p);
            j += 8;
        }
        // cleanup
        for (; j < mm2; j += 2) SPMM_PAIR(j);
#undef SPMM_PAIR
    }

    // combine the two half-warps (each accumulated every other edge)
    acc0.x += __shfl_xor_sync(0xffffffffu, acc0.x, 16);
    acc0.y += __shfl_xor_sync(0xffffffffu, acc0.y, 16);
    acc0.z += __shfl_xor_sync(0xffffffffu, acc0.z, 16);
    acc0.w += __shfl_xor_sync(0xffffffffu, acc0.w, 16);
    acc1.x += __shfl_xor_sync(0xffffffffu, acc1.x, 16);
    acc1.y += __shfl_xor_sync(0xffffffffu, acc1.y, 16);
    acc1.z += __shfl_xor_sync(0xffffffffu, acc1.z, 16);
    acc1.w += __shfl_xor_sync(0xffffffffu, acc1.w, 16);

    float4 outv = (sub == 0) ? acc0 : acc1;
    size_t off = ((size_t)sub) * CH + ((size_t)r << 6) + 4 * laneq;
    *(float4*)(Hout + off) = outv;
}

// ---------------- fused: combine + linear1 + relu + projection (block 2) ------
__global__ __launch_bounds__(256) void k_lin_proj(const float* __restrict__ linW,
                                                  const float* __restrict__ linb,
                                                  const float* __restrict__ Ws) {
    extern __shared__ float sm[];
    float* lsm = sm;             // 8192 floats
    float* psm = sm + 8192;      // 8192 floats
    for (int i = threadIdx.x; i < 2 * HD * HD; i += 256) {
        lsm[i] = __ldg(&linW[i]);
        psm[i] = __ldg(&Ws[i]);
    }
    __syncthreads();
    int warp = threadIdx.x >> 5, lane = threadIdx.x & 31;
    int rowBase = blockIdx.x * 64;
    const float2* __restrict__ lw = (const float2*)lsm;
    const float2* __restrict__ w0 = (const float2*)psm;
    const float2* __restrict__ w1 = (const float2*)(psm + HD * HD);
    float2 bias = {__ldg(&linb[2 * lane]), __ldg(&linb[2 * lane + 1])};
    for (int rr = warp; rr < 64; rr += 8) {
        int row = rowBase + rr;
        if (row >= NN) break;
        float xv[4];
#pragma unroll
        for (int t = 0; t < 4; t++) {
            int k = lane + 32 * t;      // k in [0,128): c = k>>6, j = k&63
            int cch = k >> 6, j = k & 63;
            size_t o = ((size_t)cch) * CH + ((size_t)row) * HD + j;
            float a = g_X0[o];
            float h = g_H0[o];
            float m = 0.5f * a + 0.5f * h;
            m = m > 0.f ? m : 0.f;
            xv[t] = 0.8f * m + 0.2f * a;
        }
        float2 acc = bias;
#pragma unroll
        for (int k = 0; k < 2 * HD; k++) {
            float xk = __shfl_sync(0xffffffffu, xv[k >> 5], k & 31);
            float2 wv = lw[k * 32 + lane];
            acc.x = fmaf(xk, wv.x, acc.x);
            acc.y = fmaf(xk, wv.y, acc.y);
        }
        acc.x = acc.x > 0.f ? acc.x : 0.f;   // Y row: lane owns cols 2*lane, 2*lane+1
        acc.y = acc.y > 0.f ? acc.y : 0.f;
        // project Y row through Ws1 (both channels) without leaving registers
        float2 a0 = {0.f, 0.f}, a1 = {0.f, 0.f};
#pragma unroll
        for (int k = 0; k < HD; k++) {
            float xk = __shfl_sync(0xffffffffu, (k & 1) ? acc.y : acc.x, k >> 1);
            float2 v0 = w0[k * 32 + lane];
            float2 v1 = w1[k * 32 + lane];
            a0.x = fmaf(xk, v0.x, a0.x); a0.y = fmaf(xk, v0.y, a0.y);
            a1.x = fmaf(xk, v1.x, a1.x); a1.y = fmaf(xk, v1.y, a1.y);
        }
        size_t o0 = ((size_t)row) * HD + 2 * lane;
        size_t o1 = o0 + CH;
        *(float2*)(g_H0 + o0) = a0;  *(float2*)(g_X0 + o0) = a0;
        *(float2*)(g_H0 + o1) = a1;  *(float2*)(g_X0 + o1) = a1;
    }
}

// ---------------- final combine + linear + relu -> d_out ----------------
__global__ __launch_bounds__(256) void k_lin(const float* __restrict__ linW,
                                             const float* __restrict__ linb,
                                             float* __restrict__ Y) {
    __shared__ float wsm[2 * HD * HD];  // 32 KB
    for (int i = threadIdx.x; i < 2 * HD * HD; i += 256) wsm[i] = __ldg(&linW[i]);
    __syncthreads();
    int warp = threadIdx.x >> 5, lane = threadIdx.x & 31;
    int rowBase = blockIdx.x * 64;
    const float2* __restrict__ wsm2 = (const float2*)wsm;
    float2 bias = {__ldg(&linb[2 * lane]), __ldg(&linb[2 * lane + 1])};
    for (int rr = warp; rr < 64; rr += 8) {
        int row = rowBase + rr;
        if (row >= NN) break;
        float xv[4];
#pragma unroll
        for (int t = 0; t < 4; t++) {
            int k = lane + 32 * t;
            int cch = k >> 6, j = k & 63;
            size_t o = ((size_t)cch) * CH + ((size_t)row) * HD + j;
            float a = g_X0[o];
            float h = g_H0[o];
            float m = 0.5f * a + 0.5f * h;
            m = m > 0.f ? m : 0.f;
            xv[t] = 0.8f * m + 0.2f * a;
        }
        float2 acc = bias;
#pragma unroll
        for (int k = 0; k < 2 * HD; k++) {
            float xk = __shfl_sync(0xffffffffu, xv[k >> 5], k & 31);
            float2 wv = wsm2[k * 32 + lane];
            acc.x = fmaf(xk, wv.x, acc.x);
            acc.y = fmaf(xk, wv.y, acc.y);
        }
        acc.x = acc.x > 0.f ? acc.x : 0.f;
        acc.y = acc.y > 0.f ? acc.y : 0.f;
        *(float2*)(Y + (size_t)row * HD + 2 * lane) = acc;
    }
}

// ---------------- launch ----------------
extern "C" void kernel_launch(void* const* d_in, const int* in_sizes, int n_in,
                              void* d_out, int out_size) {
    const float* X     = (const float*)d_in[0];
    const float* ev0   = (const float*)d_in[1];
    const float* ev1   = (const float*)d_in[2];
    const float* ev2   = (const float*)d_in[3];
    const float* Ws0   = (const float*)d_in[4];
    const float* Ws1   = (const float*)d_in[5];
    const float* lW0   = (const float*)d_in[6];
    const float* lW1   = (const float*)d_in[7];
    const float* linW0 = (const float*)d_in[8];
    const float* linb0 = (const float*)d_in[9];
    const float* linW1 = (const float*)d_in[10];
    const float* linb1 = (const float*)d_in[11];
    const int*   ei0   = (const int*)d_in[12];
    const int*   ei1   = (const int*)d_in[13];
    const int*   ei2   = (const int*)d_in[14];

    cudaFuncSetAttribute(k_lin_proj, cudaFuncAttributeMaxDynamicSharedMemorySize,
                         16384 * sizeof(float));

    // ---- CSR build overlapped with block-1 projection (g_cnt arrives zeroed;
    //      k_scan1 restores the invariant) ----
    k_hist_proj<<<PROJ_BLKS + HIST_BLKS, 256>>>(X, Ws0, ei0, ei1, ei2);   // 1
    k_scan1<<<(NN + SCAN_CHUNK - 1) / SCAN_CHUNK, SCAN_T>>>();            // 2
    k_scan3<<<(NN + 255) / 256, 256>>>();                                 // 3
    k_scatter<<<(ETOT + 255) / 256, 256>>>(ei0, ei1, ei2, ev0, ev1, ev2); // 4

    dim3 gs((NN + 7) / 8);

    // ---- block 1 GT layers ----
    k_spmm<<<gs, 256>>>(0, lW0);             // 5  <- ncu window target
    k_spmm<<<gs, 256>>>(1, lW0 + CC * TT);   // 6

    // ---- block1 epilogue fused with block2 projection ----
    k_lin_proj<<<PROJ_BLKS, 256, 16384 * sizeof(float)>>>(linW0, linb0, Ws1); // 7

    // ---- block 2 GT layers + output ----
    k_spmm<<<gs, 256>>>(0, lW1);             // 8
    k_spmm<<<gs, 256>>>(1, lW1 + CC * TT);   // 9
    k_lin<<<PROJ_BLKS, 256>>>(linW1, linb1, (float*)d_out);               // 10
}

// round 12
// speedup vs baseline: 1.1596x; 1.0705x over previous
#include <cuda_runtime.h>
#include <cuda_fp16.h>

#define NN   50000
#define EE   300000
#define ETOT 900000
#define CC   2
#define TT   3
#define HD   64
#define CH   ((size_t)NN * HD)          // per-channel plane size (elements)
// scan config
#define SCAN_T 512
#define SCAN_I 8
#define SCAN_CHUNK (SCAN_T * SCAN_I)    // 4096

#define PROJ_BLKS ((NN + 63) / 64)          // 782
#define HIST_BLKS ((ETOT + 1023) / 1024)    // 879

// ---------------- device scratch (static, allowed; zero-initialized at load) --
__device__ int    g_cnt[NN];              // invariant: zero at kernel_launch entry
__device__ int    g_rowptr[NN + 1];
__device__ int    g_cursor[NN];
__device__ int    g_bsum[64];
__device__ int2   g_edge[ETOT];           // {col | (etype<<28), float bits}
__device__ __half g_H0[(size_t)CC * NN * HD];   // fp16 ping plane
__device__ __half g_H1[(size_t)CC * NN * HD];   // fp16 pong plane
__device__ float  g_X0[(size_t)CC * NN * HD];   // fp32 teleport state

// ---------------- fused: histogram (CSR degree) + projection (block 1) --------
__global__ __launch_bounds__(256) void k_hist_proj(
        const float* __restrict__ X, const float* __restrict__ Ws,
        const int* __restrict__ ei0, const int* __restrict__ ei1,
        const int* __restrict__ ei2) {
    if (blockIdx.x < PROJ_BLKS) {
        __shared__ float wsm[2 * HD * HD];  // 32 KB
        for (int i = threadIdx.x; i < 2 * HD * HD; i += 256) wsm[i] = __ldg(&Ws[i]);
        __syncthreads();
        int warp = threadIdx.x >> 5, lane = threadIdx.x & 31;
        int rowBase = blockIdx.x * 64;
        const float2* __restrict__ w0 = (const float2*)wsm;
        const float2* __restrict__ w1 = (const float2*)(wsm + HD * HD);
        for (int rr = warp; rr < 64; rr += 8) {
            int row = rowBase + rr;
            if (row >= NN) break;
            float x0 = X[(size_t)row * HD + lane];
            float x1 = X[(size_t)row * HD + 32 + lane];
            float2 a0 = {0.f, 0.f}, a1 = {0.f, 0.f};
#pragma unroll
            for (int k = 0; k < HD; k++) {
                float xk = __shfl_sync(0xffffffffu, (k < 32) ? x0 : x1, k & 31);
                float2 v0 = w0[k * 32 + lane];
                float2 v1 = w1[k * 32 + lane];
                a0.x = fmaf(xk, v0.x, a0.x); a0.y = fmaf(xk, v0.y, a0.y);
                a1.x = fmaf(xk, v1.x, a1.x); a1.y = fmaf(xk, v1.y, a1.y);
            }
            size_t o0 = ((size_t)row) * HD + 2 * lane;
            size_t o1 = o0 + CH;
            __half2 h0 = __floats2half2_rn(a0.x, a0.y);
            __half2 h1 = __floats2half2_rn(a1.x, a1.y);
            *(__half2*)(g_H0 + o0) = h0;  *(float2*)(g_X0 + o0) = a0;
            *(__half2*)(g_H0 + o1) = h1;  *(float2*)(g_X0 + o1) = a1;
        }
    } else {
        int base = (blockIdx.x - PROJ_BLKS) * 1024 + threadIdx.x;
#pragma unroll
        for (int k = 0; k < 4; k++) {
            int e = base + k * 256;
            if (e >= ETOT) break;
            const int* ei; int le;
            if (e < EE)           { ei = ei0; le = e; }
            else if (e < 2 * EE)  { ei = ei1; le = e - EE; }
            else                  { ei = ei2; le = e - 2 * EE; }
            atomicAdd(&g_cnt[ei[le]], 1);
        }
    }
}

// ---------------- CSR scan (consumes AND re-zeroes g_cnt) ----------------
__global__ void k_scan1() {
    __shared__ int s[SCAN_T];
    int t = threadIdx.x;
    int base = blockIdx.x * SCAN_CHUNK + t * SCAN_I;
    int v[SCAN_I];
    int sum = 0;
#pragma unroll
    for (int i = 0; i < SCAN_I; i++) {
        int idx = base + i;
        v[i] = (idx < NN) ? g_cnt[idx] : 0;
        if (idx < NN) g_cnt[idx] = 0;      // restore invariant for next launch
        sum += v[i];
    }
    s[t] = sum;
    __syncthreads();
    for (int off = 1; off < SCAN_T; off <<= 1) {
        int x = (t >= off) ? s[t - off] : 0;
        __syncthreads();
        if (t >= off) s[t] += x;
        __syncthreads();
    }
    int excl = s[t] - sum;
    if (t == SCAN_T - 1) g_bsum[blockIdx.x] = s[t];
    int run = excl;
#pragma unroll
    for (int i = 0; i < SCAN_I; i++) {
        int idx = base + i;
        if (idx < NN) g_rowptr[idx] = run;
        run += v[i];
    }
}

__global__ void k_scan3() {
    int i = blockIdx.x * blockDim.x + threadIdx.x;
    if (i >= NN) return;
    int blk = i / SCAN_CHUNK;
    int off = 0;
    for (int b = 0; b < blk; b++) off += g_bsum[b];
    int val = g_rowptr[i] + off;
    g_rowptr[i] = val;
    g_cursor[i] = val;
    if (i == 0) g_rowptr[NN] = ETOT;
}

__global__ void k_scatter(const int* __restrict__ ei0, const int* __restrict__ ei1,
                          const int* __restrict__ ei2,
                          const float* __restrict__ ev0, const float* __restrict__ ev1,
                          const float* __restrict__ ev2) {
    int e = blockIdx.x * blockDim.x + threadIdx.x;
    if (e >= ETOT) return;
    const int* ei; const float* ev; int le; int t;
    if (e < EE)          { ei = ei0; ev = ev0; le = e;           t = 0; }
    else if (e < 2 * EE) { ei = ei1; ev = ev1; le = e - EE;      t = 1; }
    else                 { ei = ei2; ev = ev2; le = e - 2 * EE;  t = 2; }
    int r   = ei[le];
    int cix = ei[EE + le];
    float v = ev[le];
    int p = atomicAdd(&g_cursor[r], 1);
    g_edge[p] = make_int2(cix | (t << 28), __float_as_int(v));
}

// ---------------- SpMM (fp16 planes, both channels, half-warp gathers) --------
// warp per row. dir=0: g_H0 -> g_H1, dir=1: g_H1 -> g_H0 (both channel planes).
// Lane loads 8 B (4 halves); 16 lanes cover one 128 B fp16 row. fp32 accum.
__global__ __launch_bounds__(256) void k_spmm(int dir, const float* __restrict__ layW) {
    const __half* __restrict__ Hin  = dir ? g_H1 : g_H0;
    __half* __restrict__       Hout = dir ? g_H0 : g_H1;
    int warp = threadIdx.x >> 5, lane = threadIdx.x & 31;
    int sub = lane >> 4, laneq = lane & 15;
    int r = blockIdx.x * 8 + warp;
    if (r >= NN) return;

    // softmax over T=3 for each channel
    float f0[TT], f1[TT];
    {
        float b0 = __ldg(&layW[0]), b1 = __ldg(&layW[1]), b2 = __ldg(&layW[2]);
        float mx = fmaxf(b0, fmaxf(b1, b2));
        float e0 = __expf(b0 - mx), e1 = __expf(b1 - mx), e2 = __expf(b2 - mx);
        float inv = 1.0f / (e0 + e1 + e2);
        f0[0] = e0 * inv; f0[1] = e1 * inv; f0[2] = e2 * inv;
        b0 = __ldg(&layW[3]); b1 = __ldg(&layW[4]); b2 = __ldg(&layW[5]);
        mx = fmaxf(b0, fmaxf(b1, b2));
        e0 = __expf(b0 - mx); e1 = __expf(b1 - mx); e2 = __expf(b2 - mx);
        inv = 1.0f / (e0 + e1 + e2);
        f1[0] = e0 * inv; f1[1] = e1 * inv; f1[2] = e2 * inv;
    }

    int start = g_rowptr[r];
    int end   = g_rowptr[r + 1];
    float4 acc0 = {0.f, 0.f, 0.f, 0.f};
    float4 acc1 = {0.f, 0.f, 0.f, 0.f};

    for (int base = start; base < end; base += 32) {
        int e = base + lane;
        float wa = 0.f, wb = 0.f;
        int ci = 0;
        if (e < end) {
            int2 md = __ldg(&g_edge[e]);
            float v = __int_as_float(md.y);
            int et  = md.x >> 28;
            ci = md.x & 0x0FFFFFFF;
            float fa = (et == 0) ? f0[0] : ((et == 1) ? f0[1] : f0[2]);
            float fb = (et == 0) ? f1[0] : ((et == 1) ? f1[1] : f1[2]);
            wa = v * fa;
            wb = v * fb;
        }
        int mm = end - base;
        if (mm > 32) mm = 32;
        int mm2 = (mm + 1) & ~1;    // lanes >= mm carry w=0, so padding is safe

#define SPMM_PAIR(J)                                                           \
        {                                                                      \
            int src = (J) + sub;                                               \
            int   cj = __shfl_sync(0xffffffffu, ci, src);                      \
            float ua = __shfl_sync(0xffffffffu, wa, src);                      \
            float ub = __shfl_sync(0xffffffffu, wb, src);                      \
            uint2 p0 = *((const uint2*)(Hin + (((size_t)cj) << 6)) + laneq);   \
            uint2 p1 = *((const uint2*)(Hin + CH + (((size_t)cj) << 6)) + laneq);\
            float2 g0 = __half22float2(*(__half2*)&p0.x);                      \
            float2 g1 = __half22float2(*(__half2*)&p0.y);                      \
            float2 g2 = __half22float2(*(__half2*)&p1.x);                      \
            float2 g3 = __half22float2(*(__half2*)&p1.y);                      \
            acc0.x = fmaf(ua, g0.x, acc0.x); acc0.y = fmaf(ua, g0.y, acc0.y);  \
            acc0.z = fmaf(ua, g1.x, acc0.z); acc0.w = fmaf(ua, g1.y, acc0.w);  \
            acc1.x = fmaf(ub, g2.x, acc1.x); acc1.y = fmaf(ub, g2.y, acc1.y);  \
            acc1.z = fmaf(ub, g3.x, acc1.z); acc1.w = fmaf(ub, g3.y, acc1.w);  \
        }

        int j = 0;
        // 8-pair tier: 16 independent LDG.64 in flight
        for (; j + 16 <= mm2; j += 16) {
#pragma unroll
            for (int p = 0; p < 8; p++) SPMM_PAIR(j + 2 * p);
        }
        // 4-pair tier
        if (j + 8 <= mm2) {
#pragma unroll
            for (int p = 0; p < 4; p++) SPMM_PAIR(j + 2 * p);
            j += 8;
        }
        // cleanup
        for (; j < mm2; j += 2) SPMM_PAIR(j);
#undef SPMM_PAIR
    }

    // combine the two half-warps (each accumulated every other edge)
    acc0.x += __shfl_xor_sync(0xffffffffu, acc0.x, 16);
    acc0.y += __shfl_xor_sync(0xffffffffu, acc0.y, 16);
    acc0.z += __shfl_xor_sync(0xffffffffu, acc0.z, 16);
    acc0.w += __shfl_xor_sync(0xffffffffu, acc0.w, 16);
    acc1.x += __shfl_xor_sync(0xffffffffu, acc1.x, 16);
    acc1.y += __shfl_xor_sync(0xffffffffu, acc1.y, 16);
    acc1.z += __shfl_xor_sync(0xffffffffu, acc1.z, 16);
    acc1.w += __shfl_xor_sync(0xffffffffu, acc1.w, 16);

    float4 outv = (sub == 0) ? acc0 : acc1;
    __half2 o01 = __floats2half2_rn(outv.x, outv.y);
    __half2 o23 = __floats2half2_rn(outv.z, outv.w);
    uint2 st;
    st.x = *(unsigned int*)&o01;
    st.y = *(unsigned int*)&o23;
    *((uint2*)(Hout + ((size_t)sub) * CH + ((size_t)r << 6)) + laneq) = st;
}

// ---------------- fused: combine + linear1 + relu + projection (block 2) ------
__global__ __launch_bounds__(256) void k_lin_proj(const float* __restrict__ linW,
                                                  const float* __restrict__ linb,
                                                  const float* __restrict__ Ws) {
    extern __shared__ float sm[];
    float* lsm = sm;             // 8192 floats
    float* psm = sm + 8192;      // 8192 floats
    for (int i = threadIdx.x; i < 2 * HD * HD; i += 256) {
        lsm[i] = __ldg(&linW[i]);
        psm[i] = __ldg(&Ws[i]);
    }
    __syncthreads();
    int warp = threadIdx.x >> 5, lane = threadIdx.x & 31;
    int rowBase = blockIdx.x * 64;
    const float2* __restrict__ lw = (const float2*)lsm;
    const float2* __restrict__ w0 = (const float2*)psm;
    const float2* __restrict__ w1 = (const float2*)(psm + HD * HD);
    float2 bias = {__ldg(&linb[2 * lane]), __ldg(&linb[2 * lane + 1])};
    for (int rr = warp; rr < 64; rr += 8) {
        int row = rowBase + rr;
        if (row >= NN) break;
        float xv[4];
#pragma unroll
        for (int t = 0; t < 4; t++) {
            int k = lane + 32 * t;      // k in [0,128): c = k>>6, j = k&63
            int cch = k >> 6, j = k & 63;
            size_t o = ((size_t)cch) * CH + ((size_t)row) * HD + j;
            float a = g_X0[o];
            float h = __half2float(g_H0[o]);
            float m = 0.5f * a + 0.5f * h;
            m = m > 0.f ? m : 0.f;
            xv[t] = 0.8f * m + 0.2f * a;
        }
        float2 acc = bias;
#pragma unroll
        for (int k = 0; k < 2 * HD; k++) {
            float xk = __shfl_sync(0xffffffffu, xv[k >> 5], k & 31);
            float2 wv = lw[k * 32 + lane];
            acc.x = fmaf(xk, wv.x, acc.x);
            acc.y = fmaf(xk, wv.y, acc.y);
        }
        acc.x = acc.x > 0.f ? acc.x : 0.f;   // Y row: lane owns cols 2*lane, 2*lane+1
        acc.y = acc.y > 0.f ? acc.y : 0.f;
        // project Y row through Ws1 (both channels) without leaving registers
        float2 a0 = {0.f, 0.f}, a1 = {0.f, 0.f};
#pragma unroll
        for (int k = 0; k < HD; k++) {
            float xk = __shfl_sync(0xffffffffu, (k & 1) ? acc.y : acc.x, k >> 1);
            float2 v0 = w0[k * 32 + lane];
            float2 v1 = w1[k * 32 + lane];
            a0.x = fmaf(xk, v0.x, a0.x); a0.y = fmaf(xk, v0.y, a0.y);
            a1.x = fmaf(xk, v1.x, a1.x); a1.y = fmaf(xk, v1.y, a1.y);
        }
        size_t o0 = ((size_t)row) * HD + 2 * lane;
        size_t o1 = o0 + CH;
        __half2 h0 = __floats2half2_rn(a0.x, a0.y);
        __half2 h1 = __floats2half2_rn(a1.x, a1.y);
        *(__half2*)(g_H0 + o0) = h0;  *(float2*)(g_X0 + o0) = a0;
        *(__half2*)(g_H0 + o1) = h1;  *(float2*)(g_X0 + o1) = a1;
    }
}

// ---------------- final combine + linear + relu -> d_out ----------------
__global__ __launch_bounds__(256) void k_lin(const float* __restrict__ linW,
                                             const float* __restrict__ linb,
                                             float* __restrict__ Y) {
    __shared__ float wsm[2 * HD * HD];  // 32 KB
    for (int i = threadIdx.x; i < 2 * HD * HD; i += 256) wsm[i] = __ldg(&linW[i]);
    __syncthreads();
    int warp = threadIdx.x >> 5, lane = threadIdx.x & 31;
    int rowBase = blockIdx.x * 64;
    const float2* __restrict__ wsm2 = (const float2*)wsm;
    float2 bias = {__ldg(&linb[2 * lane]), __ldg(&linb[2 * lane + 1])};
    for (int rr = warp; rr < 64; rr += 8) {
        int row = rowBase + rr;
        if (row >= NN) break;
        float xv[4];
#pragma unroll
        for (int t = 0; t < 4; t++) {
            int k = lane + 32 * t;
            int cch = k >> 6, j = k & 63;
            size_t o = ((size_t)cch) * CH + ((size_t)row) * HD + j;
            float a = g_X0[o];
            float h = __half2float(g_H0[o]);
            float m = 0.5f * a + 0.5f * h;
            m = m > 0.f ? m : 0.f;
            xv[t] = 0.8f * m + 0.2f * a;
        }
        float2 acc = bias;
#pragma unroll
        for (int k = 0; k < 2 * HD; k++) {
            float xk = __shfl_sync(0xffffffffu, xv[k >> 5], k & 31);
            float2 wv = wsm2[k * 32 + lane];
            acc.x = fmaf(xk, wv.x, acc.x);
            acc.y = fmaf(xk, wv.y, acc.y);
        }
        acc.x = acc.x > 0.f ? acc.x : 0.f;
        acc.y = acc.y > 0.f ? acc.y : 0.f;
        *(float2*)(Y + (size_t)row * HD + 2 * lane) = acc;
    }
}

// ---------------- launch ----------------
extern "C" void kernel_launch(void* const* d_in, const int* in_sizes, int n_in,
                              void* d_out, int out_size) {
    const float* X     = (const float*)d_in[0];
    const float* ev0   = (const float*)d_in[1];
    const float* ev1   = (const float*)d_in[2];
    const float* ev2   = (const float*)d_in[3];
    const float* Ws0   = (const float*)d_in[4];
    const float* Ws1   = (const float*)d_in[5];
    const float* lW0   = (const float*)d_in[6];
    const float* lW1   = (const float*)d_in[7];
    const float* linW0 = (const float*)d_in[8];
    const float* linb0 = (const float*)d_in[9];
    const float* linW1 = (const float*)d_in[10];
    const float* linb1 = (const float*)d_in[11];
    const int*   ei0   = (const int*)d_in[12];
    const int*   ei1   = (const int*)d_in[13];
    const int*   ei2   = (const int*)d_in[14];

    cudaFuncSetAttribute(k_lin_proj, cudaFuncAttributeMaxDynamicSharedMemorySize,
                         16384 * sizeof(float));

    // ---- CSR build overlapped with block-1 projection (g_cnt arrives zeroed;
    //      k_scan1 restores the invariant) ----
    k_hist_proj<<<PROJ_BLKS + HIST_BLKS, 256>>>(X, Ws0, ei0, ei1, ei2);   // 1
    k_scan1<<<(NN + SCAN_CHUNK - 1) / SCAN_CHUNK, SCAN_T>>>();            // 2
    k_scan3<<<(NN + 255) / 256, 256>>>();                                 // 3
    k_scatter<<<(ETOT + 255) / 256, 256>>>(ei0, ei1, ei2, ev0, ev1, ev2); // 4

    dim3 gs((NN + 7) / 8);

    // ---- block 1 GT layers ----
    k_spmm<<<gs, 256>>>(0, lW0);             // 5
    k_spmm<<<gs, 256>>>(1, lW0 + CC * TT);   // 6

    // ---- block1 epilogue fused with block2 projection ----
    k_lin_proj<<<PROJ_BLKS, 256, 16384 * sizeof(float)>>>(linW0, linb0, Ws1); // 7

    // ---- block 2 GT layers + output ----
    k_spmm<<<gs, 256>>>(0, lW1);             // 8
    k_spmm<<<gs, 256>>>(1, lW1 + CC * TT);   // 9
    k_lin<<<PROJ_BLKS, 256>>>(linW1, linb1, (float*)d_out);               // 10
}